// round 1
// baseline (speedup 1.0000x reference)
#include <cuda_runtime.h>
#include <cstdint>

// Problem constants
#define B_ 96
#define S_ 128
#define C_ 141
#define D_ 768
#define M_ (B_ * S_)     // 12288 rows
#define N_ (2 * D_)      // 1536 cols
#define K_ (2 * D_)      // 1536 reduction

// Scratch for X = concat(h0,h1) @ W^T + b  (75.5 MB, static device array — no allocs)
__device__ float g_X[(size_t)M_ * N_];

// ---------------------------------------------------------------------------
// Packed f32x2 helpers (sm_103a): 3-reg FFMA is half-rate on B300; the packed
// fma.rn.f32x2 form does 2 fp32 FMAs per issue slot.
// ---------------------------------------------------------------------------
__device__ __forceinline__ unsigned long long pack2_dup(float a) {
    unsigned long long r;
    asm("mov.b64 %0, {%1, %1};" : "=l"(r) : "f"(a));
    return r;
}
__device__ __forceinline__ unsigned long long fma2(unsigned long long a,
                                                   unsigned long long b,
                                                   unsigned long long c) {
    unsigned long long d;
    asm("fma.rn.f32x2 %0, %1, %2, %3;" : "=l"(d) : "l"(a), "l"(b), "l"(c));
    return d;
}
__device__ __forceinline__ unsigned long long add2(unsigned long long a,
                                                   unsigned long long b) {
    unsigned long long d;
    asm("add.rn.f32x2 %0, %1, %2;" : "=l"(d) : "l"(a), "l"(b));
    return d;
}

// ---------------------------------------------------------------------------
// GEMM: X[m][n] = sum_k A[m][k] * W[n][k] + bias[n]
//   A[m][k] = k < 768 ? h0[m*768 + k] : h1[m*768 + k - 768]
// Tiling: BM=BN=128, BK=8, 256 threads, 8x8 outputs/thread (packed as 8x4 f32x2),
// double-buffered shared memory.
// ---------------------------------------------------------------------------
#define BM 128
#define BN 128
#define BK 8

__global__ __launch_bounds__(256, 2)
void gemm_kernel(const float* __restrict__ h0, const float* __restrict__ h1,
                 const float* __restrict__ W, const float* __restrict__ bias) {
    __shared__ float As[2][BK][BM];
    __shared__ float Bs[2][BK][BN];

    const int tid = threadIdx.x;
    const int m0  = blockIdx.y * BM;
    const int n0  = blockIdx.x * BN;

    // Global-load mapping: 256 threads load a 128x8 tile as 256 float4s.
    const int lrow = tid >> 1;            // 0..127
    const int lcol = (tid & 1) << 2;      // 0 or 4

    // Compute-thread mapping: 16x16 threads, each owns 8(M) x 8(N).
    const int ty = tid >> 4;              // 0..15  (M direction)
    const int tx = tid & 15;              // 0..15  (N direction)

    const float* A0 = h0 + (size_t)(m0 + lrow) * D_;
    const float* A1 = h1 + (size_t)(m0 + lrow) * D_;
    const float* Wp = W  + (size_t)(n0 + lrow) * K_;

    unsigned long long acc[8][4];
    #pragma unroll
    for (int i = 0; i < 8; i++)
        #pragma unroll
        for (int j = 0; j < 4; j++) acc[i][j] = 0ULL;

    // Preload tile 0 (k0 = 0 < D_, so A source is h0)
    {
        float4 av = *(const float4*)(A0 + lcol);
        float4 bv = *(const float4*)(Wp + lcol);
        As[0][lcol + 0][lrow] = av.x;
        As[0][lcol + 1][lrow] = av.y;
        As[0][lcol + 2][lrow] = av.z;
        As[0][lcol + 3][lrow] = av.w;
        Bs[0][lcol + 0][lrow] = bv.x;
        Bs[0][lcol + 1][lrow] = bv.y;
        Bs[0][lcol + 2][lrow] = bv.z;
        Bs[0][lcol + 3][lrow] = bv.w;
    }
    __syncthreads();

    int buf = 0;
    const int T = K_ / BK;  // 192 k-tiles

    for (int t = 0; t < T; t++) {
        float4 av2, bv2;
        if (t + 1 < T) {
            const int k0 = (t + 1) * BK;
            const float* Asrc = (k0 < D_) ? (A0 + k0) : (A1 + (k0 - D_));
            av2 = *(const float4*)(Asrc + lcol);
            bv2 = *(const float4*)(Wp + k0 + lcol);
        }

        #pragma unroll
        for (int k = 0; k < BK; k++) {
            float4 ra0 = *(const float4*)&As[buf][k][ty * 8];
            float4 ra1 = *(const float4*)&As[buf][k][ty * 8 + 4];
            const unsigned long long* bp =
                (const unsigned long long*)&Bs[buf][k][tx * 8];
            unsigned long long rn0 = bp[0], rn1 = bp[1], rn2 = bp[2], rn3 = bp[3];

            unsigned long long rm[8];
            rm[0] = pack2_dup(ra0.x);
            rm[1] = pack2_dup(ra0.y);
            rm[2] = pack2_dup(ra0.z);
            rm[3] = pack2_dup(ra0.w);
            rm[4] = pack2_dup(ra1.x);
            rm[5] = pack2_dup(ra1.y);
            rm[6] = pack2_dup(ra1.z);
            rm[7] = pack2_dup(ra1.w);

            #pragma unroll
            for (int i = 0; i < 8; i++) {
                acc[i][0] = fma2(rm[i], rn0, acc[i][0]);
                acc[i][1] = fma2(rm[i], rn1, acc[i][1]);
                acc[i][2] = fma2(rm[i], rn2, acc[i][2]);
                acc[i][3] = fma2(rm[i], rn3, acc[i][3]);
            }
        }

        if (t + 1 < T) {
            buf ^= 1;
            As[buf][lcol + 0][lrow] = av2.x;
            As[buf][lcol + 1][lrow] = av2.y;
            As[buf][lcol + 2][lrow] = av2.z;
            As[buf][lcol + 3][lrow] = av2.w;
            Bs[buf][lcol + 0][lrow] = bv2.x;
            Bs[buf][lcol + 1][lrow] = bv2.y;
            Bs[buf][lcol + 2][lrow] = bv2.z;
            Bs[buf][lcol + 3][lrow] = bv2.w;
            __syncthreads();
        }
    }

    // Epilogue: add bias (packed) and store.
    const unsigned long long* bias2 =
        (const unsigned long long*)(bias + n0 + tx * 8);
    unsigned long long bb[4];
    #pragma unroll
    for (int j = 0; j < 4; j++) bb[j] = bias2[j];

    #pragma unroll
    for (int i = 0; i < 8; i++) {
        const int m = m0 + ty * 8 + i;
        unsigned long long* xr =
            (unsigned long long*)(g_X + (size_t)m * N_ + n0 + tx * 8);
        #pragma unroll
        for (int j = 0; j < 4; j++) xr[j] = add2(acc[i][j], bb[j]);
    }
}

// ---------------------------------------------------------------------------
// Fused tokmap + gather:
//   One block per (b, c). Threads 0..127 scan tokens for coverage and
//   atomicMax the winning (max) token id into shared; then 192 threads copy
//   768 floats (as float4) for each of start/end halves (or zeros if invalid).
// Output layout: [start_result (B,C,D) | end_result (B,C,D)], both fp32.
// ---------------------------------------------------------------------------
__global__ __launch_bounds__(192)
void gather_kernel(const int* __restrict__ om, float* __restrict__ out) {
    const int b = blockIdx.x / C_;
    const int c = blockIdx.x % C_;

    __shared__ int stok;
    if (threadIdx.x == 0) stok = -1;
    __syncthreads();

    const int s = threadIdx.x;
    if (s < S_) {
        const int st = om[((size_t)b * S_ + s) * 2 + 0];
        const int en = om[((size_t)b * S_ + s) * 2 + 1];
        if (c >= st && c < en) atomicMax(&stok, s);
    }
    __syncthreads();

    const int t = stok;
    float4 sv, ev;
    if (t >= 0) {
        const float4* xs =
            (const float4*)(g_X + (size_t)(b * S_ + t) * N_);
        sv = xs[threadIdx.x];          // cols [0, 768)   -> start half
        ev = xs[192 + threadIdx.x];    // cols [768,1536) -> end half
    } else {
        sv = make_float4(0.f, 0.f, 0.f, 0.f);
        ev = sv;
    }

    float4* o4 = (float4*)out;
    const size_t row = (size_t)(b * C_ + c) * 192;
    o4[row + threadIdx.x] = sv;
    o4[(size_t)B_ * C_ * 192 + row + threadIdx.x] = ev;
}

// ---------------------------------------------------------------------------
extern "C" void kernel_launch(void* const* d_in, const int* in_sizes, int n_in,
                              void* d_out, int out_size) {
    const float* h0   = (const float*)d_in[0];
    const float* h1   = (const float*)d_in[1];
    const float* W    = (const float*)d_in[2];
    const float* bias = (const float*)d_in[3];
    const int*   om   = (const int*)d_in[4];
    float* out = (float*)d_out;

    dim3 ggrid(N_ / BN, M_ / BM);   // 12 x 96
    gemm_kernel<<<ggrid, 256>>>(h0, h1, W, bias);

    gather_kernel<<<B_ * C_, 192>>>(om, out);
}

// round 9
// speedup vs baseline: 2.2083x; 2.2083x over previous
#include <cuda_runtime.h>
#include <cuda_bf16.h>
#include <cstdint>

// ---------------- problem constants ----------------
#define B_ 96
#define S_ 128
#define C_ 141
#define D_ 768
#define M_ (B_ * S_)     // 12288
#define N_ (2 * D_)      // 1536
#define K_ (2 * D_)      // 1536

// ---------------- GEMM tiling ----------------
#define BM 128
#define BN 128
#define BK 32
#define TCH (K_ / BK)    // 48 k-chunks

// SMEM: per stage, A and B tiles of 128 rows x 128B.
// Each row: [hi 32xbf16 (64B) | lo 32xbf16 (64B)], SW128-XOR swizzled.
#define TILE_BYTES (128 * 128)        // 16 KB
#define SM_A(s) ((s) * 2 * TILE_BYTES)
#define SM_B(s) ((s) * 2 * TILE_BYTES + TILE_BYTES)
#define SM_BIAS (4 * TILE_BYTES)      // 65536
#define SMEM_TOTAL (SM_BIAS + BN * 4) // 66048 bytes

// Scratch: X = concat(h0,h1) @ W^T + b  (75.5 MB static)
__device__ float g_X[(size_t)M_ * N_];

__device__ __forceinline__ uint32_t swz(uint32_t o) { return o ^ ((o >> 3) & 0x70); }

__device__ __forceinline__ uint32_t smem_u32(const void* p) {
    uint32_t a;
    asm("{ .reg .u64 t; cvta.to.shared.u64 t, %1; cvt.u32.u64 %0, t; }"
        : "=r"(a) : "l"(p));
    return a;
}

// pack 2 fp32 -> bf16x2 (e0 in lower half)
__device__ __forceinline__ uint32_t packbf(float e0, float e1) {
    uint32_t d;
    asm("cvt.rn.bf16x2.f32 %0, %1, %2;" : "=r"(d) : "f"(e1), "f"(e0));
    return d;
}

__device__ __forceinline__ void ldsm4(uint32_t* r, uint32_t addr) {
    asm volatile("ldmatrix.sync.aligned.m8n8.x4.shared.b16 {%0,%1,%2,%3}, [%4];"
        : "=r"(r[0]), "=r"(r[1]), "=r"(r[2]), "=r"(r[3]) : "r"(addr));
}

__device__ __forceinline__ void mma16816(float* d, const uint32_t* a,
                                         uint32_t b0, uint32_t b1) {
    asm volatile(
        "mma.sync.aligned.m16n8k16.row.col.f32.bf16.bf16.f32 "
        "{%0,%1,%2,%3}, {%4,%5,%6,%7}, {%8,%9}, {%0,%1,%2,%3};"
        : "+f"(d[0]), "+f"(d[1]), "+f"(d[2]), "+f"(d[3])
        : "r"(a[0]), "r"(a[1]), "r"(a[2]), "r"(a[3]), "r"(b0), "r"(b1));
}

// Store one float4 (4 consecutive k of one row) as hi/lo bf16 into a tile row.
__device__ __forceinline__ void cvt_sts(char* tile, int row, int c, float4 v) {
    uint32_t h01 = packbf(v.x, v.y);
    uint32_t h23 = packbf(v.z, v.w);
    float l0 = v.x - __uint_as_float(h01 << 16);
    float l1 = v.y - __uint_as_float(h01 & 0xFFFF0000u);
    float l2 = v.z - __uint_as_float(h23 << 16);
    float l3 = v.w - __uint_as_float(h23 & 0xFFFF0000u);
    uint32_t q01 = packbf(l0, l1);
    uint32_t q23 = packbf(l2, l3);
    uint32_t oh = row * 128 + c * 2;        // hi at cols [0,32)
    uint32_t ol = oh + 64;                  // lo at cols [32,64)
    *(uint2*)(tile + swz(oh)) = make_uint2(h01, h23);
    *(uint2*)(tile + swz(ol)) = make_uint2(q01, q23);
}

// ---------------------------------------------------------------------------
// Split-bf16 GEMM via mma.sync: g_X[m][n] = sum_k A[m][k]*W[n][k] + bias[n]
//   A[m][k] = k < 768 ? h0 : h1.   D = Ah*Bh + Ah*Bl + Al*Bh.
// ---------------------------------------------------------------------------
__global__ void __launch_bounds__(256)
gemm_mma(const float* __restrict__ h0, const float* __restrict__ h1,
         const float* __restrict__ W, const float* __restrict__ bias) {
    extern __shared__ __align__(128) char sm[];
    const uint32_t sb = smem_u32(sm);
    const int tid = threadIdx.x;
    const int wid = tid >> 5, lane = tid & 31;
    const int m0 = blockIdx.y * BM, n0 = blockIdx.x * BN;
    const int warp_m = wid & 1;   // 2 x 64 rows
    const int warp_n = wid >> 1;  // 4 x 32 cols

    if (tid < BN) ((float*)(sm + SM_BIAS))[tid] = bias[n0 + tid];

    // Loader mapping: 2 threads per row, 16 fp32 (4 float4) each.
    const int lrow = tid >> 1;
    const int lseg = tid & 1;

    // ldmatrix lane address components (bytes within tile)
    uint32_t arowb[4], browb[2];
    #pragma unroll
    for (int mt = 0; mt < 4; mt++)
        arowb[mt] = (uint32_t)(warp_m * 64 + mt * 16 + (lane & 7) +
                               8 * ((lane >> 3) & 1)) * 128;
    #pragma unroll
    for (int np = 0; np < 2; np++)
        browb[np] = (uint32_t)(warp_n * 32 + np * 16 + (lane & 7) +
                               8 * (lane >> 4)) * 128;
    const uint32_t laneKA = (uint32_t)(lane >> 4) * 16;        // bytes
    const uint32_t laneKB = (uint32_t)((lane >> 3) & 1) * 16;  // bytes

    float4 ra[4], rb[4];

    // ---- prologue: load + store stage 0 ----
    {
        const int kb = 0 * BK + lseg * 16;
        const float* arow = h0 + (size_t)(m0 + lrow) * D_ + kb;
        const float* wrow = W + (size_t)(n0 + lrow) * K_ + kb;
        #pragma unroll
        for (int i = 0; i < 4; i++) {
            ra[i] = *(const float4*)(arow + i * 4);
            rb[i] = *(const float4*)(wrow + i * 4);
        }
        char* aT = sm + SM_A(0);
        char* bT = sm + SM_B(0);
        #pragma unroll
        for (int i = 0; i < 4; i++) {
            int c = lseg * 16 + i * 4;
            cvt_sts(aT, lrow, c, ra[i]);
            cvt_sts(bT, lrow, c, rb[i]);
        }
    }
    __syncthreads();

    float acc[4][4][4];
    #pragma unroll
    for (int mt = 0; mt < 4; mt++)
        #pragma unroll
        for (int nt = 0; nt < 4; nt++)
            #pragma unroll
            for (int j = 0; j < 4; j++) acc[mt][nt][j] = 0.f;

    for (int t = 0; t < TCH; t++) {
        // prefetch next chunk into registers
        if (t + 1 < TCH) {
            const int kb = (t + 1) * BK + lseg * 16;
            const float* Ab = (kb < D_) ? (h0 + kb) : (h1 + (kb - D_));
            const float* arow = Ab + (size_t)(m0 + lrow) * D_;
            const float* wrow = W + (size_t)(n0 + lrow) * K_ + kb;
            #pragma unroll
            for (int i = 0; i < 4; i++) {
                ra[i] = *(const float4*)(arow + i * 4);
                rb[i] = *(const float4*)(wrow + i * 4);
            }
        }

        // compute on stage t&1
        const uint32_t aBase = sb + SM_A(t & 1);
        const uint32_t bBase = sb + SM_B(t & 1);
        #pragma unroll
        for (int ks = 0; ks < 2; ks++) {
            const uint32_t k0b = ks * 32;  // 16 bf16 = 32 bytes
            uint32_t aF[16], bH[8], bL[8];

            #pragma unroll
            for (int mt = 0; mt < 4; mt++)
                ldsm4(aF + mt * 4, aBase + swz(arowb[mt] + k0b + laneKA));
            #pragma unroll
            for (int np = 0; np < 2; np++)
                ldsm4(bH + np * 4, bBase + swz(browb[np] + k0b + laneKB));

            // hh
            #pragma unroll
            for (int mt = 0; mt < 4; mt++)
                #pragma unroll
                for (int nt = 0; nt < 4; nt++) {
                    const uint32_t* b = bH + (nt >> 1) * 4 + (nt & 1) * 2;
                    mma16816(acc[mt][nt], aF + mt * 4, b[0], b[1]);
                }

            // hl (A-hi x B-lo)
            #pragma unroll
            for (int np = 0; np < 2; np++)
                ldsm4(bL + np * 4, bBase + swz(browb[np] + k0b + laneKB + 64));
            #pragma unroll
            for (int mt = 0; mt < 4; mt++)
                #pragma unroll
                for (int nt = 0; nt < 4; nt++) {
                    const uint32_t* b = bL + (nt >> 1) * 4 + (nt & 1) * 2;
                    mma16816(acc[mt][nt], aF + mt * 4, b[0], b[1]);
                }

            // lh (A-lo x B-hi), reuse aF
            #pragma unroll
            for (int mt = 0; mt < 4; mt++)
                ldsm4(aF + mt * 4, aBase + swz(arowb[mt] + k0b + laneKA + 64));
            #pragma unroll
            for (int mt = 0; mt < 4; mt++)
                #pragma unroll
                for (int nt = 0; nt < 4; nt++) {
                    const uint32_t* b = bH + (nt >> 1) * 4 + (nt & 1) * 2;
                    mma16816(acc[mt][nt], aF + mt * 4, b[0], b[1]);
                }
        }

        // store prefetched chunk into the other stage
        if (t + 1 < TCH) {
            char* aT = sm + SM_A((t + 1) & 1);
            char* bT = sm + SM_B((t + 1) & 1);
            #pragma unroll
            for (int i = 0; i < 4; i++) {
                int c = lseg * 16 + i * 4;
                cvt_sts(aT, lrow, c, ra[i]);
                cvt_sts(bT, lrow, c, rb[i]);
            }
        }
        __syncthreads();
    }

    // ---- epilogue: bias + store to g_X ----
    const float* bs = (const float*)(sm + SM_BIAS);
    const int rbase = m0 + warp_m * 64 + (lane >> 2);
    const int cloc0 = warp_n * 32 + (lane & 3) * 2;
    #pragma unroll
    for (int mt = 0; mt < 4; mt++) {
        #pragma unroll
        for (int nt = 0; nt < 4; nt++) {
            const int cl = cloc0 + nt * 8;
            const float b0v = bs[cl], b1v = bs[cl + 1];
            const int row = rbase + mt * 16;
            float2 v0 = make_float2(acc[mt][nt][0] + b0v, acc[mt][nt][1] + b1v);
            float2 v1 = make_float2(acc[mt][nt][2] + b0v, acc[mt][nt][3] + b1v);
            *(float2*)(g_X + (size_t)row * N_ + n0 + cl) = v0;
            *(float2*)(g_X + (size_t)(row + 8) * N_ + n0 + cl) = v1;
        }
    }
}

// ---------------------------------------------------------------------------
// Fused tokmap + gather (unchanged from R1: 20.9us measured)
// ---------------------------------------------------------------------------
__global__ __launch_bounds__(192)
void gather_kernel(const int* __restrict__ om, float* __restrict__ out) {
    const int b = blockIdx.x / C_;
    const int c = blockIdx.x % C_;

    __shared__ int stok;
    if (threadIdx.x == 0) stok = -1;
    __syncthreads();

    const int s = threadIdx.x;
    if (s < S_) {
        const int st = om[((size_t)b * S_ + s) * 2 + 0];
        const int en = om[((size_t)b * S_ + s) * 2 + 1];
        if (c >= st && c < en) atomicMax(&stok, s);
    }
    __syncthreads();

    const int t = stok;
    float4 sv, ev;
    if (t >= 0) {
        const float4* xs = (const float4*)(g_X + (size_t)(b * S_ + t) * N_);
        sv = xs[threadIdx.x];
        ev = xs[192 + threadIdx.x];
    } else {
        sv = make_float4(0.f, 0.f, 0.f, 0.f);
        ev = sv;
    }

    float4* o4 = (float4*)out;
    const size_t row = (size_t)(b * C_ + c) * 192;
    o4[row + threadIdx.x] = sv;
    o4[(size_t)B_ * C_ * 192 + row + threadIdx.x] = ev;
}

// ---------------------------------------------------------------------------
extern "C" void kernel_launch(void* const* d_in, const int* in_sizes, int n_in,
                              void* d_out, int out_size) {
    const float* h0   = (const float*)d_in[0];
    const float* h1   = (const float*)d_in[1];
    const float* W    = (const float*)d_in[2];
    const float* bias = (const float*)d_in[3];
    const int*   om   = (const int*)d_in[4];
    float* out = (float*)d_out;

    cudaFuncSetAttribute(gemm_mma, cudaFuncAttributeMaxDynamicSharedMemorySize,
                         SMEM_TOTAL);

    dim3 ggrid(N_ / BN, M_ / BM);   // (12, 96)
    gemm_mma<<<ggrid, 256, SMEM_TOTAL>>>(h0, h1, W, bias);

    gather_kernel<<<B_ * C_, 192>>>(om, out);
}

// round 12
// speedup vs baseline: 3.6305x; 1.6440x over previous
#include <cuda_runtime.h>
#include <cuda_bf16.h>
#include <cstdint>

// ---------------- problem constants ----------------
#define B_ 96
#define S_ 128
#define C_ 141
#define D_ 768
#define M_ (B_ * S_)     // 12288
#define N_ (2 * D_)      // 1536
#define K_ (2 * D_)      // 1536

// ---------------- GEMM tiling ----------------
#define BM 64
#define BN 128
#define BK 32
#define TCH (K_ / BK)    // 48 k-chunks

// SMEM: per stage, A tile 64 rows x 128B, B tile 128 rows x 128B.
// Each row: [hi 32xbf16 (64B) | lo 32xbf16 (64B)], SW128-XOR swizzled.
#define SM_A(s) ((s) * 8192)                 // 2 x 8 KB
#define SM_B(s) (16384 + (s) * 16384)        // 2 x 16 KB
#define SM_BIAS 49152                        // 128 floats
#define SMEM_TOTAL (SM_BIAS + BN * 4)        // 49664 bytes

// Scratch (compact-row X) + token maps
__device__ float g_X[(size_t)M_ * N_];
__device__ int g_tokmap[B_ * C_];
__device__ int g_list[B_ * S_];
__device__ int g_cidx[B_ * S_];
__device__ int g_cnt[B_];

__device__ __forceinline__ uint32_t swz(uint32_t o) { return o ^ ((o >> 3) & 0x70); }

__device__ __forceinline__ uint32_t smem_u32(const void* p) {
    uint32_t a;
    asm("{ .reg .u64 t; cvta.to.shared.u64 t, %1; cvt.u32.u64 %0, t; }"
        : "=r"(a) : "l"(p));
    return a;
}

__device__ __forceinline__ uint32_t packbf(float e0, float e1) {
    uint32_t d;
    asm("cvt.rn.bf16x2.f32 %0, %1, %2;" : "=r"(d) : "f"(e1), "f"(e0));
    return d;
}

__device__ __forceinline__ void ldsm4(uint32_t* r, uint32_t addr) {
    asm volatile("ldmatrix.sync.aligned.m8n8.x4.shared.b16 {%0,%1,%2,%3}, [%4];"
        : "=r"(r[0]), "=r"(r[1]), "=r"(r[2]), "=r"(r[3]) : "r"(addr));
}

__device__ __forceinline__ void mma16816(float* d, const uint32_t* a,
                                         uint32_t b0, uint32_t b1) {
    asm volatile(
        "mma.sync.aligned.m16n8k16.row.col.f32.bf16.bf16.f32 "
        "{%0,%1,%2,%3}, {%4,%5,%6,%7}, {%8,%9}, {%0,%1,%2,%3};"
        : "+f"(d[0]), "+f"(d[1]), "+f"(d[2]), "+f"(d[3])
        : "r"(a[0]), "r"(a[1]), "r"(a[2]), "r"(a[3]), "r"(b0), "r"(b1));
}

__device__ __forceinline__ void cvt_sts(char* tile, int row, int c, float4 v) {
    uint32_t h01 = packbf(v.x, v.y);
    uint32_t h23 = packbf(v.z, v.w);
    float l0 = v.x - __uint_as_float(h01 << 16);
    float l1 = v.y - __uint_as_float(h01 & 0xFFFF0000u);
    float l2 = v.z - __uint_as_float(h23 << 16);
    float l3 = v.w - __uint_as_float(h23 & 0xFFFF0000u);
    uint32_t q01 = packbf(l0, l1);
    uint32_t q23 = packbf(l2, l3);
    uint32_t oh = row * 128 + c * 2;
    uint32_t ol = oh + 64;
    *(uint2*)(tile + swz(oh)) = make_uint2(h01, h23);
    *(uint2*)(tile + swz(ol)) = make_uint2(q01, q23);
}

// ---------------------------------------------------------------------------
// Prep: tokmap (char -> covering token; intervals are disjoint so the unique
// cover is the max), compact used-token list, inverse index, counts.
// One block per batch.
// ---------------------------------------------------------------------------
__global__ __launch_bounds__(192)
void prep_kernel(const int* __restrict__ om) {
    const int b = blockIdx.x;
    const int tid = threadIdx.x;
    __shared__ int st[S_], en[S_], used[S_], psum[S_ + 1];

    if (tid < S_) {
        st[tid] = om[((size_t)b * S_ + tid) * 2 + 0];
        en[tid] = om[((size_t)b * S_ + tid) * 2 + 1];
        used[tid] = (st[tid] < en[tid]) ? 1 : 0;
    }
    __syncthreads();

    for (int c = tid; c < C_; c += blockDim.x) {
        int tm = -1;
        #pragma unroll 8
        for (int s = 0; s < S_; s++)
            if (c >= st[s] && c < en[s]) tm = s;    // ascending -> max wins
        g_tokmap[b * C_ + c] = tm;
    }

    if (tid == 0) {
        int acc = 0;
        for (int s = 0; s < S_; s++) { psum[s] = acc; acc += used[s]; }
        psum[S_] = acc;
        g_cnt[b] = acc;
    }
    __syncthreads();

    if (tid < S_) {
        g_cidx[b * S_ + tid] = psum[tid];
        if (used[tid]) g_list[b * S_ + psum[tid]] = tid;
    }
    const int total = psum[S_];
    for (int j = total + tid; j < S_; j += blockDim.x)
        g_list[b * S_ + j] = 0;                     // pad (rows never gathered)
}

// ---------------------------------------------------------------------------
// Split-bf16 GEMM over COMPACTED rows:
//   g_X[b*128 + j][n] = A[b, list[b][j]] . W[n] + bias[n]
// CTA: 64(M, compact) x 128(N). blockIdx.y = b*2 + half; empty halves exit.
// D = Ah*Bh + Ah*Bl + Al*Bh.
// ---------------------------------------------------------------------------
__global__ void __launch_bounds__(256)
gemm_mma(const float* __restrict__ h0, const float* __restrict__ h1,
         const float* __restrict__ W, const float* __restrict__ bias) {
    const int b = blockIdx.y >> 1;
    const int half = blockIdx.y & 1;
    if (half * BM >= g_cnt[b]) return;              // empty tile

    extern __shared__ __align__(128) char sm[];
    const uint32_t sb = smem_u32(sm);
    const int tid = threadIdx.x;
    const int wid = tid >> 5, lane = tid & 31;
    const int n0 = blockIdx.x * BN;
    const int warp_m = wid & 1;   // 2 x 32 rows
    const int warp_n = wid >> 1;  // 4 x 32 cols

    if (tid < BN) ((float*)(sm + SM_BIAS))[tid] = bias[n0 + tid];

    // A loader: 4 threads/row (8 fp32 each); B loader: 2 threads/row (16 fp32)
    const int lrowA = tid >> 2, lsegA = tid & 3;
    const int lrowB = tid >> 1, lsegB = tid & 1;

    // indirect A row
    const int tok = g_list[b * S_ + half * BM + lrowA];
    const size_t aoff = ((size_t)b * S_ + tok) * D_;
    const float* wrowp = W + (size_t)(n0 + lrowB) * K_;

    // ldmatrix lane addresses (bytes within tile)
    uint32_t arowb[2], browb[2];
    #pragma unroll
    for (int mt = 0; mt < 2; mt++)
        arowb[mt] = (uint32_t)(warp_m * 32 + mt * 16 + (lane & 7) +
                               8 * ((lane >> 3) & 1)) * 128;
    #pragma unroll
    for (int np = 0; np < 2; np++)
        browb[np] = (uint32_t)(warp_n * 32 + np * 16 + (lane & 7) +
                               8 * (lane >> 4)) * 128;
    const uint32_t laneKA = (uint32_t)(lane >> 4) * 16;
    const uint32_t laneKB = (uint32_t)((lane >> 3) & 1) * 16;

    float4 ra[2], rb[4];

    // ---- prologue: chunk 0 (k < 768 -> h0) ----
    {
        const int kb = lsegA * 8;
        const float* ar = h0 + aoff + kb;
        ra[0] = *(const float4*)(ar);
        ra[1] = *(const float4*)(ar + 4);
        const int kw = lsegB * 16;
        #pragma unroll
        for (int i = 0; i < 4; i++) rb[i] = *(const float4*)(wrowp + kw + i * 4);
        char* aT = sm + SM_A(0);
        char* bT = sm + SM_B(0);
        cvt_sts(aT, lrowA, lsegA * 8, ra[0]);
        cvt_sts(aT, lrowA, lsegA * 8 + 4, ra[1]);
        #pragma unroll
        for (int i = 0; i < 4; i++) cvt_sts(bT, lrowB, lsegB * 16 + i * 4, rb[i]);
    }
    __syncthreads();

    float acc[2][4][4];
    #pragma unroll
    for (int mt = 0; mt < 2; mt++)
        #pragma unroll
        for (int nt = 0; nt < 4; nt++)
            #pragma unroll
            for (int j = 0; j < 4; j++) acc[mt][nt][j] = 0.f;

    for (int t = 0; t < TCH; t++) {
        if (t + 1 < TCH) {
            const int kb = (t + 1) * BK + lsegA * 8;
            const float* ar = (kb < D_) ? (h0 + aoff + kb) : (h1 + aoff + kb - D_);
            ra[0] = *(const float4*)(ar);
            ra[1] = *(const float4*)(ar + 4);
            const int kw = (t + 1) * BK + lsegB * 16;
            #pragma unroll
            for (int i = 0; i < 4; i++) rb[i] = *(const float4*)(wrowp + kw + i * 4);
        }

        const uint32_t aBase = sb + SM_A(t & 1);
        const uint32_t bBase = sb + SM_B(t & 1);
        #pragma unroll
        for (int ks = 0; ks < 2; ks++) {
            const uint32_t k0b = ks * 32;
            uint32_t aF[8], bH[8], bL[8];

            #pragma unroll
            for (int mt = 0; mt < 2; mt++)
                ldsm4(aF + mt * 4, aBase + swz(arowb[mt] + k0b + laneKA));
            #pragma unroll
            for (int np = 0; np < 2; np++)
                ldsm4(bH + np * 4, bBase + swz(browb[np] + k0b + laneKB));

            // hh
            #pragma unroll
            for (int mt = 0; mt < 2; mt++)
                #pragma unroll
                for (int nt = 0; nt < 4; nt++) {
                    const uint32_t* bb = bH + (nt >> 1) * 4 + (nt & 1) * 2;
                    mma16816(acc[mt][nt], aF + mt * 4, bb[0], bb[1]);
                }

            // hl
            #pragma unroll
            for (int np = 0; np < 2; np++)
                ldsm4(bL + np * 4, bBase + swz(browb[np] + k0b + laneKB + 64));
            #pragma unroll
            for (int mt = 0; mt < 2; mt++)
                #pragma unroll
                for (int nt = 0; nt < 4; nt++) {
                    const uint32_t* bb = bL + (nt >> 1) * 4 + (nt & 1) * 2;
                    mma16816(acc[mt][nt], aF + mt * 4, bb[0], bb[1]);
                }

            // lh
            #pragma unroll
            for (int mt = 0; mt < 2; mt++)
                ldsm4(aF + mt * 4, aBase + swz(arowb[mt] + k0b + laneKA + 64));
            #pragma unroll
            for (int mt = 0; mt < 2; mt++)
                #pragma unroll
                for (int nt = 0; nt < 4; nt++) {
                    const uint32_t* bb = bH + (nt >> 1) * 4 + (nt & 1) * 2;
                    mma16816(acc[mt][nt], aF + mt * 4, bb[0], bb[1]);
                }
        }

        if (t + 1 < TCH) {
            char* aT = sm + SM_A((t + 1) & 1);
            char* bT = sm + SM_B((t + 1) & 1);
            cvt_sts(aT, lrowA, lsegA * 8, ra[0]);
            cvt_sts(aT, lrowA, lsegA * 8 + 4, ra[1]);
            #pragma unroll
            for (int i = 0; i < 4; i++)
                cvt_sts(bT, lrowB, lsegB * 16 + i * 4, rb[i]);
        }
        __syncthreads();
    }

    // ---- epilogue ----
    const float* bs = (const float*)(sm + SM_BIAS);
    const int rloc = warp_m * 32 + (lane >> 2);
    const int cloc0 = warp_n * 32 + (lane & 3) * 2;
    const size_t rowbase = (size_t)b * S_ + half * BM;
    #pragma unroll
    for (int mt = 0; mt < 2; mt++) {
        #pragma unroll
        for (int nt = 0; nt < 4; nt++) {
            const int cl = cloc0 + nt * 8;
            const float b0v = bs[cl], b1v = bs[cl + 1];
            const size_t row = rowbase + rloc + mt * 16;
            float2 v0 = make_float2(acc[mt][nt][0] + b0v, acc[mt][nt][1] + b1v);
            float2 v1 = make_float2(acc[mt][nt][2] + b0v, acc[mt][nt][3] + b1v);
            *(float2*)(g_X + row * N_ + n0 + cl) = v0;
            *(float2*)(g_X + (row + 8) * N_ + n0 + cl) = v1;
        }
    }
}

// ---------------------------------------------------------------------------
// Gather from compacted X via tokmap + cidx
// ---------------------------------------------------------------------------
__global__ __launch_bounds__(192)
void gather_kernel(float* __restrict__ out) {
    const int b = blockIdx.x / C_;
    const int c = blockIdx.x % C_;

    const int t = g_tokmap[b * C_ + c];
    float4 sv, ev;
    if (t >= 0) {
        const int j = g_cidx[b * S_ + t];
        const float4* xs = (const float4*)(g_X + ((size_t)b * S_ + j) * N_);
        sv = xs[threadIdx.x];
        ev = xs[192 + threadIdx.x];
    } else {
        sv = make_float4(0.f, 0.f, 0.f, 0.f);
        ev = sv;
    }

    float4* o4 = (float4*)out;
    const size_t row = (size_t)(b * C_ + c) * 192;
    o4[row + threadIdx.x] = sv;
    o4[(size_t)B_ * C_ * 192 + row + threadIdx.x] = ev;
}

// ---------------------------------------------------------------------------
extern "C" void kernel_launch(void* const* d_in, const int* in_sizes, int n_in,
                              void* d_out, int out_size) {
    const float* h0   = (const float*)d_in[0];
    const float* h1   = (const float*)d_in[1];
    const float* W    = (const float*)d_in[2];
    const float* bias = (const float*)d_in[3];
    const int*   om   = (const int*)d_in[4];
    float* out = (float*)d_out;

    cudaFuncSetAttribute(gemm_mma, cudaFuncAttributeMaxDynamicSharedMemorySize,
                         SMEM_TOTAL);

    prep_kernel<<<B_, 192>>>(om);

    dim3 ggrid(N_ / BN, B_ * 2);   // (12, 192); ~half exit immediately
    gemm_mma<<<ggrid, 256, SMEM_TOTAL>>>(h0, h1, W, bias);

    gather_kernel<<<B_ * C_, 192>>>(out);
}

// round 17
// speedup vs baseline: 4.2383x; 1.1674x over previous
#include <cuda_runtime.h>
#include <cuda_fp16.h>
#include <cstdint>

// ---------------- problem constants ----------------
#define B_ 96
#define S_ 128
#define C_ 141
#define D_ 768
#define M_ (B_ * S_)     // 12288
#define N_ (2 * D_)      // 1536
#define K_ (2 * D_)      // 1536

// ---------------- GEMM tiling ----------------
#define BM 64
#define BN 256
#define BK 32
#define TCH (K_ / BK)    // 48 k-chunks

// SMEM: per stage, A tile 64 rows x 64B (32 fp16), B tile 256 rows x 64B.
// XOR swizzle: bits[4:5] ^= bits[7:8]  (conflict-free ldmatrix on 64B rows).
#define SM_A(s) ((s) * 4096)                 // 2 x 4 KB
#define SM_B(s) (8192 + (s) * 16384)         // 2 x 16 KB
#define SM_BIAS 40960                        // 256 floats
#define SMEM_TOTAL (SM_BIAS + BN * 4)        // 41984 bytes

// Scratch (compact-row X) + token maps
__device__ float g_X[(size_t)M_ * N_];
__device__ int g_tokmap[B_ * C_];
__device__ int g_list[B_ * S_];
__device__ int g_cidx[B_ * S_];
__device__ int g_cnt[B_];

__device__ __forceinline__ uint32_t swz64(uint32_t o) { return o ^ ((o >> 3) & 0x30); }

__device__ __forceinline__ uint32_t smem_u32(const void* p) {
    uint32_t a;
    asm("{ .reg .u64 t; cvta.to.shared.u64 t, %1; cvt.u32.u64 %0, t; }"
        : "=r"(a) : "l"(p));
    return a;
}

__device__ __forceinline__ void ldsm4(uint32_t* r, uint32_t addr) {
    asm volatile("ldmatrix.sync.aligned.m8n8.x4.shared.b16 {%0,%1,%2,%3}, [%4];"
        : "=r"(r[0]), "=r"(r[1]), "=r"(r[2]), "=r"(r[3]) : "r"(addr));
}

__device__ __forceinline__ void mma16816(float* d, const uint32_t* a,
                                         uint32_t b0, uint32_t b1) {
    asm volatile(
        "mma.sync.aligned.m16n8k16.row.col.f32.f16.f16.f32 "
        "{%0,%1,%2,%3}, {%4,%5,%6,%7}, {%8,%9}, {%0,%1,%2,%3};"
        : "+f"(d[0]), "+f"(d[1]), "+f"(d[2]), "+f"(d[3])
        : "r"(a[0]), "r"(a[1]), "r"(a[2]), "r"(a[3]), "r"(b0), "r"(b1));
}

// Store 4 consecutive k of one row as fp16 (8B) into a 64B-row swizzled tile.
__device__ __forceinline__ void cvt_sts16(char* tile, int row, int c, float4 v) {
    __half2 h01 = __floats2half2_rn(v.x, v.y);   // x in low half (k ascending)
    __half2 h23 = __floats2half2_rn(v.z, v.w);
    uint32_t o = (uint32_t)row * 64 + (uint32_t)c * 2;
    o = swz64(o);
    *(uint2*)(tile + o) = make_uint2(*(uint32_t*)&h01, *(uint32_t*)&h23);
}

// ---------------------------------------------------------------------------
// Prep: tokmap, compact used-token list, inverse index, counts. 1 block/batch.
// ---------------------------------------------------------------------------
__global__ __launch_bounds__(192)
void prep_kernel(const int* __restrict__ om) {
    const int b = blockIdx.x;
    const int tid = threadIdx.x;
    __shared__ int st[S_], en[S_], used[S_], psum[S_ + 1];

    if (tid < S_) {
        st[tid] = om[((size_t)b * S_ + tid) * 2 + 0];
        en[tid] = om[((size_t)b * S_ + tid) * 2 + 1];
        used[tid] = (st[tid] < en[tid]) ? 1 : 0;
    }
    __syncthreads();

    for (int c = tid; c < C_; c += blockDim.x) {
        int tm = -1;
        #pragma unroll 8
        for (int s = 0; s < S_; s++)
            if (c >= st[s] && c < en[s]) tm = s;    // ascending -> max wins
        g_tokmap[b * C_ + c] = tm;
    }

    if (tid == 0) {
        int acc = 0;
        for (int s = 0; s < S_; s++) { psum[s] = acc; acc += used[s]; }
        psum[S_] = acc;
        g_cnt[b] = acc;
    }
    __syncthreads();

    if (tid < S_) {
        g_cidx[b * S_ + tid] = psum[tid];
        if (used[tid]) g_list[b * S_ + psum[tid]] = tid;
    }
    const int total = psum[S_];
    for (int j = total + tid; j < S_; j += blockDim.x)
        g_list[b * S_ + j] = 0;                     // pad (rows never gathered)
}

// ---------------------------------------------------------------------------
// fp16 single-pass GEMM over COMPACTED rows:
//   g_X[b*128 + j][n] = A[b, list[b][j]] . W[n] + bias[n]
// CTA: 64(M) x 256(N); 8 warps 1x8, each 64x32. Empty halves exit.
// ---------------------------------------------------------------------------
__global__ void __launch_bounds__(256)
gemm_mma(const float* __restrict__ h0, const float* __restrict__ h1,
         const float* __restrict__ W, const float* __restrict__ bias) {
    const int b = blockIdx.y >> 1;
    const int half = blockIdx.y & 1;
    if (half * BM >= g_cnt[b]) return;              // empty tile

    extern __shared__ __align__(128) char sm[];
    const uint32_t sb = smem_u32(sm);
    const int tid = threadIdx.x;
    const int wid = tid >> 5, lane = tid & 31;
    const int n0 = blockIdx.x * BN;

    ((float*)(sm + SM_BIAS))[tid] = bias[n0 + tid];   // BN == blockDim

    // A loader: 4 threads/row (8 fp32 each); B loader: 1 thread/row (32 fp32)
    const int lrowA = tid >> 2, lsegA = tid & 3;
    const int lrowB = tid;

    // indirect A row
    const int tok = g_list[b * S_ + half * BM + lrowA];
    const size_t aoff = ((size_t)b * S_ + tok) * D_;
    const float* wrowp = W + (size_t)(n0 + lrowB) * K_;

    // ldmatrix lane addresses (bytes within tile, 64B rows)
    uint32_t arowb[4], browb[2];
    #pragma unroll
    for (int mt = 0; mt < 4; mt++)
        arowb[mt] = (uint32_t)(mt * 16 + (lane & 7) + 8 * ((lane >> 3) & 1)) * 64;
    #pragma unroll
    for (int np = 0; np < 2; np++)
        browb[np] = (uint32_t)(wid * 32 + np * 16 + (lane & 7) +
                               8 * (lane >> 4)) * 64;
    const uint32_t laneKA = (uint32_t)(lane >> 4) * 16;
    const uint32_t laneKB = (uint32_t)((lane >> 3) & 1) * 16;

    float4 ra[2], rb[8];

    // ---- prologue: chunk 0 (k < 768 -> h0) ----
    {
        const float* ar = h0 + aoff + lsegA * 8;
        ra[0] = *(const float4*)(ar);
        ra[1] = *(const float4*)(ar + 4);
        #pragma unroll
        for (int i = 0; i < 8; i++) rb[i] = *(const float4*)(wrowp + i * 4);
        char* aT = sm + SM_A(0);
        char* bT = sm + SM_B(0);
        cvt_sts16(aT, lrowA, lsegA * 8, ra[0]);
        cvt_sts16(aT, lrowA, lsegA * 8 + 4, ra[1]);
        #pragma unroll
        for (int i = 0; i < 8; i++) cvt_sts16(bT, lrowB, i * 4, rb[i]);
    }
    __syncthreads();

    float acc[4][4][4];
    #pragma unroll
    for (int mt = 0; mt < 4; mt++)
        #pragma unroll
        for (int nt = 0; nt < 4; nt++)
            #pragma unroll
            for (int j = 0; j < 4; j++) acc[mt][nt][j] = 0.f;

    for (int t = 0; t < TCH; t++) {
        if (t + 1 < TCH) {
            const int kb = (t + 1) * BK + lsegA * 8;
            const float* ar = (kb < D_) ? (h0 + aoff + kb) : (h1 + aoff + kb - D_);
            ra[0] = *(const float4*)(ar);
            ra[1] = *(const float4*)(ar + 4);
            const int kw = (t + 1) * BK;
            #pragma unroll
            for (int i = 0; i < 8; i++) rb[i] = *(const float4*)(wrowp + kw + i * 4);
        }

        const uint32_t aBase = sb + SM_A(t & 1);
        const uint32_t bBase = sb + SM_B(t & 1);
        #pragma unroll
        for (int ks = 0; ks < 2; ks++) {
            const uint32_t k0b = ks * 32;          // 16 fp16 = 32 bytes
            uint32_t aF[16], bF[8];

            #pragma unroll
            for (int mt = 0; mt < 4; mt++)
                ldsm4(aF + mt * 4, aBase + swz64(arowb[mt] + k0b + laneKA));
            #pragma unroll
            for (int np = 0; np < 2; np++)
                ldsm4(bF + np * 4, bBase + swz64(browb[np] + k0b + laneKB));

            #pragma unroll
            for (int mt = 0; mt < 4; mt++)
                #pragma unroll
                for (int nt = 0; nt < 4; nt++) {
                    const uint32_t* bb = bF + (nt >> 1) * 4 + (nt & 1) * 2;
                    mma16816(acc[mt][nt], aF + mt * 4, bb[0], bb[1]);
                }
        }

        if (t + 1 < TCH) {
            char* aT = sm + SM_A((t + 1) & 1);
            char* bT = sm + SM_B((t + 1) & 1);
            cvt_sts16(aT, lrowA, lsegA * 8, ra[0]);
            cvt_sts16(aT, lrowA, lsegA * 8 + 4, ra[1]);
            #pragma unroll
            for (int i = 0; i < 8; i++)
                cvt_sts16(bT, lrowB, i * 4, rb[i]);
        }
        __syncthreads();
    }

    // ---- epilogue ----
    const float* bs = (const float*)(sm + SM_BIAS);
    const int rloc = lane >> 2;
    const int cloc0 = wid * 32 + (lane & 3) * 2;
    const size_t rowbase = (size_t)b * S_ + half * BM;
    #pragma unroll
    for (int mt = 0; mt < 4; mt++) {
        #pragma unroll
        for (int nt = 0; nt < 4; nt++) {
            const int cl = cloc0 + nt * 8;
            const float b0v = bs[cl], b1v = bs[cl + 1];
            const size_t row = rowbase + mt * 16 + rloc;
            float2 v0 = make_float2(acc[mt][nt][0] + b0v, acc[mt][nt][1] + b1v);
            float2 v1 = make_float2(acc[mt][nt][2] + b0v, acc[mt][nt][3] + b1v);
            *(float2*)(g_X + row * N_ + n0 + cl) = v0;
            *(float2*)(g_X + (row + 8) * N_ + n0 + cl) = v1;
        }
    }
}

// ---------------------------------------------------------------------------
// Gather from compacted X via tokmap + cidx
// ---------------------------------------------------------------------------
__global__ __launch_bounds__(192)
void gather_kernel(float* __restrict__ out) {
    const int b = blockIdx.x / C_;
    const int c = blockIdx.x % C_;

    const int t = g_tokmap[b * C_ + c];
    float4 sv, ev;
    if (t >= 0) {
        const int j = g_cidx[b * S_ + t];
        const float4* xs = (const float4*)(g_X + ((size_t)b * S_ + j) * N_);
        sv = xs[threadIdx.x];
        ev = xs[192 + threadIdx.x];
    } else {
        sv = make_float4(0.f, 0.f, 0.f, 0.f);
        ev = sv;
    }

    float4* o4 = (float4*)out;
    const size_t row = (size_t)(b * C_ + c) * 192;
    o4[row + threadIdx.x] = sv;
    o4[(size_t)B_ * C_ * 192 + row + threadIdx.x] = ev;
}

// ---------------------------------------------------------------------------
extern "C" void kernel_launch(void* const* d_in, const int* in_sizes, int n_in,
                              void* d_out, int out_size) {
    const float* h0   = (const float*)d_in[0];
    const float* h1   = (const float*)d_in[1];
    const float* W    = (const float*)d_in[2];
    const float* bias = (const float*)d_in[3];
    const int*   om   = (const int*)d_in[4];
    float* out = (float*)d_out;

    cudaFuncSetAttribute(gemm_mma, cudaFuncAttributeMaxDynamicSharedMemorySize,
                         SMEM_TOTAL);

    prep_kernel<<<B_, 192>>>(om);

    dim3 ggrid(N_ / BN, B_ * 2);   // (6, 192); ~half exit immediately
    gemm_mma<<<ggrid, 256, SMEM_TOTAL>>>(h0, h1, W, bias);

    gather_kernel<<<B_ * C_, 192>>>(out);
}